// round 1
// baseline (speedup 1.0000x reference)
#include <cuda_runtime.h>
#include <cstdint>

#define H 128
#define NLABEL 5
#define DEPTH 18
#define NLEAF (1 << (DEPTH - 1))   /* 131072 nodes at the leaf level */

// ---------------- device scratch (static, no allocation) ----------------
__device__ float g_Wx[512 * H];          // stacked [Wix;Wox;Wux;Wfx], row-major [512][128]
__device__ float g_bx[512];              // bix,box,bux,bfx
__device__ float g_Wh[384 * H];          // stacked [Wih;Woh;Wuh]
__device__ float g_bh[384];              // bih,boh,buh
__device__ float g_XG[(size_t)NLEAF * 512];   // gate pre-activations per level
__device__ float g_FH[(size_t)NLEAF * H];     // Wfh @ child_h per child
__device__ float g_hbuf[2][(size_t)NLEAF * H];
__device__ float g_cbuf[2][(size_t)NLEAF * H];
__device__ double g_loss[1024];

// ---------------- weight packing + loss zeroing ----------------
__global__ void pack_kernel(
    const float* __restrict__ Wix, const float* __restrict__ Wox,
    const float* __restrict__ Wux, const float* __restrict__ Wfx,
    const float* __restrict__ bix, const float* __restrict__ box_,
    const float* __restrict__ bux, const float* __restrict__ bfx,
    const float* __restrict__ Wih, const float* __restrict__ Woh,
    const float* __restrict__ Wuh,
    const float* __restrict__ bih, const float* __restrict__ boh,
    const float* __restrict__ buh)
{
    int idx = blockIdx.x * blockDim.x + threadIdx.x;
    if (idx < 512 * H) {
        int r = idx / H, c = idx % H, g = r >> 7, lr = r & 127;
        const float* W = (g == 0) ? Wix : (g == 1) ? Wox : (g == 2) ? Wux : Wfx;
        g_Wx[idx] = W[lr * H + c];
        if (c == 0) {
            const float* b = (g == 0) ? bix : (g == 1) ? box_ : (g == 2) ? bux : bfx;
            g_bx[r] = b[lr];
        }
    }
    if (idx < 384 * H) {
        int r = idx / H, c = idx % H, g = r >> 7, lr = r & 127;
        const float* W = (g == 0) ? Wih : (g == 1) ? Woh : Wuh;
        g_Wh[idx] = W[lr * H + c];
        if (c == 0) {
            const float* b = (g == 0) ? bih : (g == 1) ? boh : buh;
            g_bh[r] = b[lr];
        }
    }
    if (idx < 1024) g_loss[idx] = 0.0;
}

// ---------------- GEMM: C[M x N] = op(A)[M x 128] @ B^T + bias ----------------
// B is row-major [N][128] (weight layout), K = 128 fixed.
// MODE 0: A row m = A + m*128
// MODE 1: A row m = A + ridx[m]*128          (embedding gather)
// MODE 2: A row m = A[2m] + A[2m+1]          (child h pair-sum)
// ACC:    C += result (used to fold the h-gate GEMM into the x-gate buffer)
template <int MODE, bool ACC>
__global__ void __launch_bounds__(256)
gemm_k128(const float* __restrict__ A, const int* __restrict__ ridx,
          const float* __restrict__ B, const float* __restrict__ bias,
          float* __restrict__ C, int M, int ldc)
{
    __shared__ float As[16][68];
    __shared__ float Bs[16][68];
    const int t = threadIdx.x;
    const int lr = t >> 2;            // 0..63
    const int lk = (t & 3) * 4;       // 0,4,8,12
    const int ty = t >> 4;            // 0..15
    const int tx = t & 15;            // 0..15
    const int brow = blockIdx.y * 64, bcol = blockIdx.x * 64;

    float acc[4][4] = {};

    const int arow = brow + lr;
    const bool avalid = arow < M;
    const float* aptr  = A;
    const float* aptr2 = A;
    if (avalid) {
        if (MODE == 0)      aptr = A + (size_t)arow * H;
        else if (MODE == 1) aptr = A + (size_t)ridx[arow] * H;
        else { aptr = A + (size_t)(2 * arow) * H; aptr2 = aptr + H; }
    }
    const float* bptr = B + (size_t)(bcol + lr) * H;

    #pragma unroll
    for (int kb = 0; kb < H; kb += 16) {
        float4 av = make_float4(0.f, 0.f, 0.f, 0.f);
        if (avalid) {
            av = *(const float4*)(aptr + kb + lk);
            if (MODE == 2) {
                float4 a2 = *(const float4*)(aptr2 + kb + lk);
                av.x += a2.x; av.y += a2.y; av.z += a2.z; av.w += a2.w;
            }
        }
        As[lk + 0][lr] = av.x; As[lk + 1][lr] = av.y;
        As[lk + 2][lr] = av.z; As[lk + 3][lr] = av.w;
        float4 bv = *(const float4*)(bptr + kb + lk);
        Bs[lk + 0][lr] = bv.x; Bs[lk + 1][lr] = bv.y;
        Bs[lk + 2][lr] = bv.z; Bs[lk + 3][lr] = bv.w;
        __syncthreads();
        #pragma unroll
        for (int k = 0; k < 16; k++) {
            float4 a = *(const float4*)&As[k][ty * 4];
            float4 b = *(const float4*)&Bs[k][tx * 4];
            acc[0][0] += a.x * b.x; acc[0][1] += a.x * b.y; acc[0][2] += a.x * b.z; acc[0][3] += a.x * b.w;
            acc[1][0] += a.y * b.x; acc[1][1] += a.y * b.y; acc[1][2] += a.y * b.z; acc[1][3] += a.y * b.w;
            acc[2][0] += a.z * b.x; acc[2][1] += a.z * b.y; acc[2][2] += a.z * b.z; acc[2][3] += a.z * b.w;
            acc[3][0] += a.w * b.x; acc[3][1] += a.w * b.y; acc[3][2] += a.w * b.z; acc[3][3] += a.w * b.w;
        }
        __syncthreads();
    }

    #pragma unroll
    for (int i = 0; i < 4; i++) {
        int row = brow + ty * 4 + i;
        if (row < M) {
            float* crow = C + (size_t)row * ldc + bcol + tx * 4;
            #pragma unroll
            for (int j = 0; j < 4; j++) {
                float v = acc[i][j] + bias[bcol + tx * 4 + j];
                if (ACC) crow[j] += v; else crow[j] = v;
            }
        }
    }
}

// ---------------- per-node gates + cell + log-softmax loss ----------------
__device__ __forceinline__ float sigm(float x) { return 1.f / (1.f + expf(-x)); }

__global__ void __launch_bounds__(128)
node_update(const float* __restrict__ XG, const float* __restrict__ FH,
            const float* __restrict__ child_c,
            float* __restrict__ out_c, float* __restrict__ out_h,
            const float* __restrict__ Wout, const float* __restrict__ bout,
            const int* __restrict__ labels,
            int isLeaf, float* __restrict__ logp_out)
{
    const int j = blockIdx.x;
    const int k = threadIdx.x;
    const float* xg = XG + (size_t)j * 512;

    float vi = xg[k], vo = xg[H + k], vu = xg[2 * H + k];
    if (isLeaf) { vi += g_bh[k]; vo += g_bh[H + k]; vu += g_bh[2 * H + k]; }
    float gi = sigm(vi);
    float go = sigm(vo);
    float gu = tanhf(vu);
    float c = gi * gu;
    if (!isLeaf) {
        float xf = xg[3 * H + k];
        size_t c0 = (size_t)(2 * j) * H + k;
        float f0 = sigm(xf + FH[c0]);
        float f1 = sigm(xf + FH[c0 + H]);
        c += f0 * child_c[c0] + f1 * child_c[c0 + H];
    }
    float h = go * tanhf(c);
    out_c[(size_t)j * H + k] = c;
    out_h[(size_t)j * H + k] = h;

    // logits: 5 dot-products over 128, warp-shuffle reduce then cross-warp
    float p[NLABEL];
    #pragma unroll
    for (int l = 0; l < NLABEL; l++) p[l] = h * Wout[l * H + k];
    #pragma unroll
    for (int off = 16; off; off >>= 1) {
        #pragma unroll
        for (int l = 0; l < NLABEL; l++)
            p[l] += __shfl_down_sync(0xffffffffu, p[l], off);
    }
    __shared__ float swarp[4][NLABEL];
    int wid = k >> 5, lane = k & 31;
    if (lane == 0) {
        #pragma unroll
        for (int l = 0; l < NLABEL; l++) swarp[wid][l] = p[l];
    }
    __syncthreads();
    if (k == 0) {
        float lg[NLABEL];
        float m = -1e30f;
        #pragma unroll
        for (int l = 0; l < NLABEL; l++) {
            lg[l] = swarp[0][l] + swarp[1][l] + swarp[2][l] + swarp[3][l] + bout[l];
            m = fmaxf(m, lg[l]);
        }
        float s = 0.f;
        #pragma unroll
        for (int l = 0; l < NLABEL; l++) s += expf(lg[l] - m);
        float lse = m + logf(s);
        int lab = labels[j];
        atomicAdd(&g_loss[j & 1023], (double)(lse - lg[lab]));
        if (logp_out) {
            #pragma unroll
            for (int l = 0; l < NLABEL; l++) logp_out[l] = lg[l] - lse;
        }
    }
}

__global__ void finalize_kernel(float* __restrict__ d_out, int out_size)
{
    __shared__ double s[256];
    int t = threadIdx.x;
    double v = g_loss[t] + g_loss[t + 256] + g_loss[t + 512] + g_loss[t + 768];
    s[t] = v;
    __syncthreads();
    for (int off = 128; off; off >>= 1) {
        if (t < off) s[t] += s[t + off];
        __syncthreads();
    }
    if (t == 0) {
        if (out_size >= NLABEL + 1) d_out[NLABEL] = (float)s[0];
        else                        d_out[0]      = (float)s[0];
    }
}

// ---------------- launch ----------------
extern "C" void kernel_launch(void* const* d_in, const int* in_sizes, int n_in,
                              void* d_out, int out_size)
{
    const float* embeds = (const float*)d_in[0];
    const int*   words  = (const int*)d_in[1];
    const int*   labels = (const int*)d_in[2];
    // d_in[3]=depth, d_in[4]=branching (compile-time constants here)
    const float* Wix = (const float*)d_in[5];
    const float* bix = (const float*)d_in[6];
    const float* Wih = (const float*)d_in[7];
    const float* bih = (const float*)d_in[8];
    const float* Wfx = (const float*)d_in[9];
    const float* bfx = (const float*)d_in[10];
    const float* Wfh = (const float*)d_in[11];
    const float* bfh = (const float*)d_in[12];
    const float* Wox = (const float*)d_in[13];
    const float* box_ = (const float*)d_in[14];
    const float* Woh = (const float*)d_in[15];
    const float* boh = (const float*)d_in[16];
    const float* Wux = (const float*)d_in[17];
    const float* bux = (const float*)d_in[18];
    const float* Wuh = (const float*)d_in[19];
    const float* buh = (const float*)d_in[20];
    const float* Wout = (const float*)d_in[21];
    const float* bout = (const float*)d_in[22];
    float* out = (float*)d_out;

    float *XG, *FH, *hbuf, *cbuf, *Wxp, *bxp, *Whp, *bhp;
    cudaGetSymbolAddress((void**)&XG,   g_XG);
    cudaGetSymbolAddress((void**)&FH,   g_FH);
    cudaGetSymbolAddress((void**)&hbuf, g_hbuf);
    cudaGetSymbolAddress((void**)&cbuf, g_cbuf);
    cudaGetSymbolAddress((void**)&Wxp,  g_Wx);
    cudaGetSymbolAddress((void**)&bxp,  g_bx);
    cudaGetSymbolAddress((void**)&Whp,  g_Wh);
    cudaGetSymbolAddress((void**)&bhp,  g_bh);

    pack_kernel<<<256, 256>>>(Wix, Wox, Wux, Wfx, bix, box_, bux, bfx,
                              Wih, Woh, Wuh, bih, boh, buh);

    const size_t lvl = (size_t)NLEAF * H;
    for (int l = DEPTH - 1; l >= 0; --l) {
        int n   = 1 << l;
        int off = n - 1;
        int cur = l & 1, chd = cur ^ 1;
        float* h_out = hbuf + (size_t)cur * lvl;
        float* c_out = cbuf + (size_t)cur * lvl;
        float* h_ch  = hbuf + (size_t)chd * lvl;
        float* c_ch  = cbuf + (size_t)chd * lvl;
        bool leaf = (l == DEPTH - 1);

        dim3 g1(8, (n + 63) / 64);
        gemm_k128<1, false><<<g1, 256>>>(embeds, words + off, Wxp, bxp, XG, n, 512);
        if (!leaf) {
            dim3 g2(6, (n + 63) / 64);
            gemm_k128<2, true><<<g2, 256>>>(h_ch, nullptr, Whp, bhp, XG, n, 512);
            dim3 g3(2, (2 * n + 63) / 64);
            gemm_k128<0, false><<<g3, 256>>>(h_ch, nullptr, Wfh, bfh, FH, 2 * n, 128);
        }
        float* logp_dst = (n == 1 && out_size >= NLABEL + 1) ? out : nullptr;
        node_update<<<n, 128>>>(XG, FH, c_ch, c_out, h_out, Wout, bout,
                                labels + off, leaf ? 1 : 0, logp_dst);
    }
    finalize_kernel<<<1, 256>>>(out, out_size);
}